// round 11
// baseline (speedup 1.0000x reference)
#include <cuda_runtime.h>

// LePEAttention: out = Q (K^T V) * 2/sqrt(32); no softmax. 128 batches (t,b,win,head),
// each: Q,K,V = [32 ch][1568 pos], pos = 56 rows x 28 cols (win selects col half).

#define HW4    784                 // 3136/4
#define NB     128
#define SROW   29                  // k/v row stride in float4 units (28 + 1 pad)
#define CH_F4  (32 * SROW)
#define BUF_F4 (2 * CH_F4)         // K + V one 4-row chunk
#define P1_SMEM (3 * BUF_F4 * 16)  // triple buffered: 89088 B
#define P2_SMEM 36864              // sQ[1792] f4 (28672 B) + sMd[1024] u64 (8192 B)
#define SCALE2 0.35355339059327373f

__device__ float g_part[NB * 2 * 1024];

#define FFMA2(d, a, b) \
    asm("fma.rn.f32x2 %0, %1, %2, %0;" : "+l"(d) : "l"(a), "l"(b))

__device__ __forceinline__ unsigned long long pack2(float x, float y) {
    unsigned long long r;
    asm("mov.b64 %0, {%1,%2};" : "=l"(r) : "f"(x), "f"(y));
    return r;
}
__device__ __forceinline__ float2 unpack2(unsigned long long a) {
    float2 f;
    asm("mov.b64 {%0,%1}, %2;" : "=f"(f.x), "=f"(f.y) : "l"(a));
    return f;
}
__device__ __forceinline__ void cp16(void* dst, const void* src) {
    unsigned d = (unsigned)__cvta_generic_to_shared(dst);
    asm volatile("cp.async.cg.shared.global [%0], [%1], 16;" :: "r"(d), "l"(src));
}

// ===== Pass 1: 448 threads, 4x4 tile, 3-stage pipeline, 28 warps/SM =====
__global__ __launch_bounds__(448, 2) void p1(const float* __restrict__ K,
                                             const float* __restrict__ V) {
    extern __shared__ float4 smem[];

    const int tid   = threadIdx.x;
    const int half  = blockIdx.x;       // rows [0,28) / [28,56)
    const int batch = blockIdx.y;
    const int h   = batch & 7;
    const int win = (batch >> 3) & 1;
    const int tb  = batch >> 4;
    const int base4 = (tb * 256 + h * 32) * HW4 + win * 7;

    const float4* Kp = (const float4*)K;
    const float4* Vp = (const float4*)V;

    // 4 load slots/thread/chunk (2 K + 2 V); 448*2 = 896 = 32ch * 28 f4
    int sm_off[4], g_off[4];
    #pragma unroll
    for (int it = 0; it < 4; ++it) {
        int ii = tid + (it & 1) * 448;            // 0..895
        int ch = ii / 28;
        int u  = ii - ch * 28;
        int r  = u / 7;
        int cu = u - r * 7;
        sm_off[it] = (it >= 2 ? CH_F4 : 0) + ch * SROW + u;
        g_off[it]  = ch * HW4 + r * 14 + cu;
    }

    const int g   = tid >> 6;           // 7 groups of 64; group covers p4 {4g..4g+3}
    const int rr  = tid & 63;
    const int d1g = rr >> 3;            // kf broadcast per 8-lane phase
    const int d2g = rr & 7;             // vf step 29 mod 8 = 5: conflict-free

    unsigned long long acc[4][4];
    #pragma unroll
    for (int i = 0; i < 4; i++)
        #pragma unroll
        for (int j = 0; j < 4; j++) acc[i][j] = 0ull;

    // prologue: chunks 0,1
    #pragma unroll
    for (int pc = 0; pc < 2; ++pc) {
        const int rb = (half * 28 + pc * 4) * 14;
        #pragma unroll
        for (int it = 0; it < 4; ++it)
            cp16(&smem[pc * BUF_F4 + sm_off[it]],
                 (it >= 2 ? Vp : Kp) + base4 + g_off[it] + rb);
        asm volatile("cp.async.commit_group;");
    }

    #pragma unroll 1
    for (int c = 0; c < 7; ++c) {
        if (c < 6) asm volatile("cp.async.wait_group 1;");
        else       asm volatile("cp.async.wait_group 0;");
        __syncthreads();

        if (c + 2 < 7) {
            const int buf = (c + 2) % 3;
            const int rb  = (half * 28 + (c + 2) * 4) * 14;
            #pragma unroll
            for (int it = 0; it < 4; ++it)
                cp16(&smem[buf * BUF_F4 + sm_off[it]],
                     (it >= 2 ? Vp : Kp) + base4 + g_off[it] + rb);
            asm volatile("cp.async.commit_group;");
        }

        const float4* sK = &smem[(c % 3) * BUF_F4];
        const float4* sV = sK + CH_F4;
        #pragma unroll
        for (int qq = 0; qq < 4; ++qq) {
            const int p4 = 4 * g + qq;
            ulonglong2 vf[4];
            #pragma unroll
            for (int j = 0; j < 4; j++)
                vf[j] = *reinterpret_cast<const ulonglong2*>(&sV[(d2g + 8 * j) * SROW + p4]);
            #pragma unroll
            for (int i = 0; i < 4; i++) {
                ulonglong2 kf =
                    *reinterpret_cast<const ulonglong2*>(&sK[(d1g + 8 * i) * SROW + p4]);
                #pragma unroll
                for (int j = 0; j < 4; j++) {
                    FFMA2(acc[i][j], kf.x, vf[j].x);
                    FFMA2(acc[i][j], kf.y, vf[j].y);
                }
            }
        }
    }

    float res[4][4];
    #pragma unroll
    for (int i = 0; i < 4; i++)
        #pragma unroll
        for (int j = 0; j < 4; j++) {
            float2 f = unpack2(acc[i][j]);
            res[i][j] = f.x + f.y;
        }

    __syncthreads();                    // buffers retired -> reuse for reduction
    float* sRed = (float*)smem;         // 6 * 1024 floats = 24 KB
    if (g) {
        #pragma unroll
        for (int i = 0; i < 4; i++)
            #pragma unroll
            for (int j = 0; j < 4; j++)
                sRed[(g - 1) * 1024 + (d1g + 8 * i) * 32 + d2g + 8 * j] = res[i][j];
    }
    __syncthreads();
    if (!g) {
        float* o = &g_part[((batch << 1) | half) << 10];
        #pragma unroll
        for (int i = 0; i < 4; i++)
            #pragma unroll
            for (int j = 0; j < 4; j++) {
                const int idx = (d1g + 8 * i) * 32 + d2g + 8 * j;
                float s = res[i][j];
                #pragma unroll
                for (int w = 0; w < 6; w++) s += sRed[w * 1024 + idx];
                o[idx] = s;
            }
    }
}

// ===== Pass 2: 1 item/CTA, pos-pair packing (M duplicated, q-pairs free) =====
// item = b*7 + rb (8-row block). 896 CTAs, 4/SM.
__global__ __launch_bounds__(224, 4) void p2(const float* __restrict__ Q,
                                             float* __restrict__ O) {
    extern __shared__ float4 dsm[];
    float4* sQ = dsm;                                   // [1792] f4
    unsigned long long* sMd = (unsigned long long*)(dsm + 1792);  // [1024] (m,m) u64

    const int tid  = threadIdx.x;
    const int item = blockIdx.x;               // 0..895
    const int b    = item / 7;
    const int rb   = item - b * 7;
    const int h    = b & 7;
    const int win  = (b >> 3) & 1;
    const int tb   = b >> 4;
    const int ibase = (tb * 256 + h * 32) * HW4 + win * 7 + rb * 112;

    const float4* Q4 = (const float4*)Q;
    float4* O4 = (float4*)O;

    // burst: whole item's q (32 ch x 56 quads = 1792 f4)
    #pragma unroll
    for (int t = 0; t < 8; ++t) {
        int i  = tid + t * 224;
        int ch = i / 56;
        int qd = i - ch * 56;
        cp16(&sQ[i], Q4 + ibase + ch * HW4 + (qd / 7) * 14 + (qd - (qd / 7) * 7));
    }
    asm volatile("cp.async.commit_group;");

    // M staging, duplicated: sMd[d*32+co] = (m,m)
    {
        const float* gp = &g_part[b << 11];
        for (int i = tid; i < 1024; i += 224) {
            float s = (gp[i] + gp[1024 + i]) * SCALE2;
            sMd[i] = pack2(s, s);
        }
    }

    asm volatile("cp.async.wait_group 0;");
    __syncthreads();

    const int cg   = tid & 3;                  // ch_out group {cg*8..cg*8+7}
    const int quad = tid >> 2;                 // 0..55
    const int base4 = ibase + (quad / 7) * 14 + (quad - (quad / 7) * 7);

    const ulonglong2* qU = reinterpret_cast<const ulonglong2*>(sQ) + quad;

    unsigned long long acc[2][8];              // [pos-pair][ch_out]
    #pragma unroll
    for (int p = 0; p < 2; p++)
        #pragma unroll
        for (int j = 0; j < 8; j++) acc[p][j] = 0ull;

    #pragma unroll
    for (int d = 0; d < 32; ++d) {
        ulonglong2 qp = qU[d * 56];            // (q0,q1),(q2,q3) packed, no MOVs
        const ulonglong2* mr =
            reinterpret_cast<const ulonglong2*>(&sMd[d * 32 + cg * 8]);
        ulonglong2 m01 = mr[0], m23 = mr[1], m45 = mr[2], m67 = mr[3];
        FFMA2(acc[0][0], qp.x, m01.x); FFMA2(acc[1][0], qp.y, m01.x);
        FFMA2(acc[0][1], qp.x, m01.y); FFMA2(acc[1][1], qp.y, m01.y);
        FFMA2(acc[0][2], qp.x, m23.x); FFMA2(acc[1][2], qp.y, m23.x);
        FFMA2(acc[0][3], qp.x, m23.y); FFMA2(acc[1][3], qp.y, m23.y);
        FFMA2(acc[0][4], qp.x, m45.x); FFMA2(acc[1][4], qp.y, m45.x);
        FFMA2(acc[0][5], qp.x, m45.y); FFMA2(acc[1][5], qp.y, m45.y);
        FFMA2(acc[0][6], qp.x, m67.x); FFMA2(acc[1][6], qp.y, m67.x);
        FFMA2(acc[0][7], qp.x, m67.y); FFMA2(acc[1][7], qp.y, m67.y);
    }

    #pragma unroll
    for (int co = 0; co < 8; ++co) {
        ulonglong2 st;
        st.x = acc[0][co];                     // (pos0,pos1)
        st.y = acc[1][co];                     // (pos2,pos3)
        *reinterpret_cast<ulonglong2*>(&O4[base4 + (cg * 8 + co) * HW4]) = st;
    }
}

extern "C" void kernel_launch(void* const* d_in, const int* in_sizes, int n_in,
                              void* d_out, int out_size) {
    const float* q = (const float*)d_in[0];
    const float* k = (const float*)d_in[1];
    const float* v = (const float*)d_in[2];
    float* o = (float*)d_out;

    cudaFuncSetAttribute(p1, cudaFuncAttributeMaxDynamicSharedMemorySize, P1_SMEM);
    cudaFuncSetAttribute(p2, cudaFuncAttributeMaxDynamicSharedMemorySize, P2_SMEM);
    p1<<<dim3(2, NB), 448, P1_SMEM>>>(k, v);
    p2<<<896, 224, P2_SMEM>>>(q, o);
}

// round 12
// speedup vs baseline: 1.1748x; 1.1748x over previous
#include <cuda_runtime.h>

// LePEAttention: out = Q (K^T V) * 2/sqrt(32); no softmax. 128 batches (t,b,win,head),
// each: Q,K,V = [32 ch][1568 pos], pos = 56 rows x 28 cols (win selects col half).

#define HW4    784                 // 3136/4
#define NB     128
#define SROW   29                  // k/v row stride in float4 units (28 + 1 pad)
#define CH_F4  (32 * SROW)
#define BUF_F4 (2 * CH_F4)         // K + V one 4-row chunk
#define P1_SMEM (3 * BUF_F4 * 16)  // triple buffered: 89088 B
#define P2_SMEM 36864              // sQ[1792] f4 (28672 B) + sMd[1024] u64 (8192 B)
#define SCALE2 0.35355339059327373f

__device__ float g_part[NB * 2 * 1024];

#define FFMA2(d, a, b) \
    asm("fma.rn.f32x2 %0, %1, %2, %0;" : "+l"(d) : "l"(a), "l"(b))

__device__ __forceinline__ unsigned long long pack2(float x, float y) {
    unsigned long long r;
    asm("mov.b64 %0, {%1,%2};" : "=l"(r) : "f"(x), "f"(y));
    return r;
}
__device__ __forceinline__ float2 unpack2(unsigned long long a) {
    float2 f;
    asm("mov.b64 {%0,%1}, %2;" : "=f"(f.x), "=f"(f.y) : "l"(a));
    return f;
}
__device__ __forceinline__ void cp16(void* dst, const void* src) {
    unsigned d = (unsigned)__cvta_generic_to_shared(dst);
    asm volatile("cp.async.cg.shared.global [%0], [%1], 16;" :: "r"(d), "l"(src));
}

// ===== Pass 1 (round-11, best p1): 448 threads, 4x4 tile, 3-stage pipeline =====
__global__ __launch_bounds__(448, 2) void p1(const float* __restrict__ K,
                                             const float* __restrict__ V) {
    extern __shared__ float4 smem[];

    const int tid   = threadIdx.x;
    const int half  = blockIdx.x;       // rows [0,28) / [28,56)
    const int batch = blockIdx.y;
    const int h   = batch & 7;
    const int win = (batch >> 3) & 1;
    const int tb  = batch >> 4;
    const int base4 = (tb * 256 + h * 32) * HW4 + win * 7;

    const float4* Kp = (const float4*)K;
    const float4* Vp = (const float4*)V;

    int sm_off[4], g_off[4];
    #pragma unroll
    for (int it = 0; it < 4; ++it) {
        int ii = tid + (it & 1) * 448;            // 0..895
        int ch = ii / 28;
        int u  = ii - ch * 28;
        int r  = u / 7;
        int cu = u - r * 7;
        sm_off[it] = (it >= 2 ? CH_F4 : 0) + ch * SROW + u;
        g_off[it]  = ch * HW4 + r * 14 + cu;
    }

    const int g   = tid >> 6;           // 7 groups of 64; group covers p4 {4g..4g+3}
    const int rr  = tid & 63;
    const int d1g = rr >> 3;            // kf broadcast per 8-lane phase
    const int d2g = rr & 7;             // vf step 29 mod 8 = 5: conflict-free

    unsigned long long acc[4][4];
    #pragma unroll
    for (int i = 0; i < 4; i++)
        #pragma unroll
        for (int j = 0; j < 4; j++) acc[i][j] = 0ull;

    #pragma unroll
    for (int pc = 0; pc < 2; ++pc) {
        const int rb = (half * 28 + pc * 4) * 14;
        #pragma unroll
        for (int it = 0; it < 4; ++it)
            cp16(&smem[pc * BUF_F4 + sm_off[it]],
                 (it >= 2 ? Vp : Kp) + base4 + g_off[it] + rb);
        asm volatile("cp.async.commit_group;");
    }

    #pragma unroll 1
    for (int c = 0; c < 7; ++c) {
        if (c < 6) asm volatile("cp.async.wait_group 1;");
        else       asm volatile("cp.async.wait_group 0;");
        __syncthreads();

        if (c + 2 < 7) {
            const int buf = (c + 2) % 3;
            const int rb  = (half * 28 + (c + 2) * 4) * 14;
            #pragma unroll
            for (int it = 0; it < 4; ++it)
                cp16(&smem[buf * BUF_F4 + sm_off[it]],
                     (it >= 2 ? Vp : Kp) + base4 + g_off[it] + rb);
            asm volatile("cp.async.commit_group;");
        }

        const float4* sK = &smem[(c % 3) * BUF_F4];
        const float4* sV = sK + CH_F4;
        #pragma unroll
        for (int qq = 0; qq < 4; ++qq) {
            const int p4 = 4 * g + qq;
            ulonglong2 vf[4];
            #pragma unroll
            for (int j = 0; j < 4; j++)
                vf[j] = *reinterpret_cast<const ulonglong2*>(&sV[(d2g + 8 * j) * SROW + p4]);
            #pragma unroll
            for (int i = 0; i < 4; i++) {
                ulonglong2 kf =
                    *reinterpret_cast<const ulonglong2*>(&sK[(d1g + 8 * i) * SROW + p4]);
                #pragma unroll
                for (int j = 0; j < 4; j++) {
                    FFMA2(acc[i][j], kf.x, vf[j].x);
                    FFMA2(acc[i][j], kf.y, vf[j].y);
                }
            }
        }
    }

    float res[4][4];
    #pragma unroll
    for (int i = 0; i < 4; i++)
        #pragma unroll
        for (int j = 0; j < 4; j++) {
            float2 f = unpack2(acc[i][j]);
            res[i][j] = f.x + f.y;
        }

    __syncthreads();
    float* sRed = (float*)smem;
    if (g) {
        #pragma unroll
        for (int i = 0; i < 4; i++)
            #pragma unroll
            for (int j = 0; j < 4; j++)
                sRed[(g - 1) * 1024 + (d1g + 8 * i) * 32 + d2g + 8 * j] = res[i][j];
    }
    __syncthreads();
    if (!g) {
        float* o = &g_part[((batch << 1) | half) << 10];
        #pragma unroll
        for (int i = 0; i < 4; i++)
            #pragma unroll
            for (int j = 0; j < 4; j++) {
                const int idx = (d1g + 8 * i) * 32 + d2g + 8 * j;
                float s = res[i][j];
                #pragma unroll
                for (int w = 0; w < 6; w++) s += sRed[w * 1024 + idx];
                o[idx] = s;
            }
    }
}

// ===== Pass 2: 448 thr, thread = quad x 4 ch_out, pair-native, 3 CTAs/SM =====
// item = b*7 + rb (8-row block). 896 CTAs.
__global__ __launch_bounds__(448, 3) void p2(const float* __restrict__ Q,
                                             float* __restrict__ O) {
    extern __shared__ float4 dsm[];
    float4* sQ = dsm;                                             // [1792] f4
    unsigned long long* sMd = (unsigned long long*)(dsm + 1792);  // [1024] (m,m)

    const int tid  = threadIdx.x;
    const int item = blockIdx.x;               // 0..895
    const int b    = item / 7;
    const int rb   = item - b * 7;
    const int h    = b & 7;
    const int win  = (b >> 3) & 1;
    const int tb   = b >> 4;
    const int ibase = (tb * 256 + h * 32) * HW4 + win * 7 + rb * 112;

    const float4* Q4 = (const float4*)Q;
    float4* O4 = (float4*)O;

    // burst: whole item's q (1792 f4), 4 cp.async per thread
    #pragma unroll
    for (int t = 0; t < 4; ++t) {
        int i  = tid + t * 448;
        int ch = i / 56;
        int qd = i - ch * 56;
        cp16(&sQ[i], Q4 + ibase + ch * HW4 + (qd / 7) * 14 + (qd - (qd / 7) * 7));
    }
    asm volatile("cp.async.commit_group;");

    // M staging (overlaps q burst): duplicated pairs, halves reduced + scale folded
    {
        const float* gp = &g_part[b << 11];
        #pragma unroll
        for (int t = 0; t < 3; ++t) {
            int i = tid + t * 448;
            if (i < 1024) {
                float s = (gp[i] + gp[1024 + i]) * SCALE2;
                sMd[i] = pack2(s, s);
            }
        }
    }

    asm volatile("cp.async.wait_group 0;");
    __syncthreads();

    const int quad = tid >> 3;                 // 0..55 (8-lane phase shares quad)
    const int cg   = tid & 7;                  // ch_out = {cg, cg+8, cg+16, cg+24}
    const int base4 = ibase + (quad / 7) * 14 + (quad - (quad / 7) * 7);

    const ulonglong2* qU = reinterpret_cast<const ulonglong2*>(sQ) + quad;
    const unsigned long long* Ms = sMd + cg;

    unsigned long long acc[2][4];              // [pos-pair][ch_out j]
    #pragma unroll
    for (int p = 0; p < 2; p++)
        #pragma unroll
        for (int j = 0; j < 4; j++) acc[p][j] = 0ull;

    #pragma unroll
    for (int d = 0; d < 32; ++d) {
        ulonglong2 qp = qU[d * 56];            // (q0,q1),(q2,q3) packed free
        const unsigned long long* mrow = Ms + d * 32;
        unsigned long long m0 = mrow[0];       // LDS.64, 8B stride per lane: CF
        unsigned long long m1 = mrow[8];
        unsigned long long m2 = mrow[16];
        unsigned long long m3 = mrow[24];
        FFMA2(acc[0][0], qp.x, m0); FFMA2(acc[1][0], qp.y, m0);
        FFMA2(acc[0][1], qp.x, m1); FFMA2(acc[1][1], qp.y, m1);
        FFMA2(acc[0][2], qp.x, m2); FFMA2(acc[1][2], qp.y, m2);
        FFMA2(acc[0][3], qp.x, m3); FFMA2(acc[1][3], qp.y, m3);
    }

    #pragma unroll
    for (int j = 0; j < 4; ++j) {
        ulonglong2 st;
        st.x = acc[0][j];                      // (pos0,pos1)
        st.y = acc[1][j];                      // (pos2,pos3)
        *reinterpret_cast<ulonglong2*>(&O4[base4 + (cg + 8 * j) * HW4]) = st;
    }
}

extern "C" void kernel_launch(void* const* d_in, const int* in_sizes, int n_in,
                              void* d_out, int out_size) {
    const float* q = (const float*)d_in[0];
    const float* k = (const float*)d_in[1];
    const float* v = (const float*)d_in[2];
    float* o = (float*)d_out;

    cudaFuncSetAttribute(p1, cudaFuncAttributeMaxDynamicSharedMemorySize, P1_SMEM);
    cudaFuncSetAttribute(p2, cudaFuncAttributeMaxDynamicSharedMemorySize, P2_SMEM);
    p1<<<dim3(2, NB), 448, P1_SMEM>>>(k, v);
    p2<<<896, 448, P2_SMEM>>>(q, o);
}

// round 13
// speedup vs baseline: 1.3876x; 1.1811x over previous
#include <cuda_runtime.h>

// LePEAttention: out = Q (K^T V) * 2/sqrt(32); no softmax. 128 batches (t,b,win,head),
// each: Q,K,V = [32 ch][1568 pos], pos = 56 rows x 28 cols (win selects col half).

#define HW4    784                 // 3136/4
#define NB     128
#define SROW   29                  // k/v row stride in float4 units (28 + 1 pad)
#define CH_F4  (32 * SROW)
#define BUF_F4 (2 * CH_F4)         // K + V one 4-row chunk
#define P1_SMEM (3 * BUF_F4 * 16)  // triple buffered: 89088 B
#define P2_SMEM 32768              // sQ[1792] f4 (28672 B) + sM[1024] f32 (4096 B)
#define SCALE2 0.35355339059327373f

__device__ float g_part[NB * 2 * 1024];

#define FFMA2(d, a, b) \
    asm("fma.rn.f32x2 %0, %1, %2, %0;" : "+l"(d) : "l"(a), "l"(b))

__device__ __forceinline__ unsigned long long pack2(float x, float y) {
    unsigned long long r;
    asm("mov.b64 %0, {%1,%2};" : "=l"(r) : "f"(x), "f"(y));
    return r;
}
__device__ __forceinline__ float2 unpack2(unsigned long long a) {
    float2 f;
    asm("mov.b64 {%0,%1}, %2;" : "=f"(f.x), "=f"(f.y) : "l"(a));
    return f;
}
__device__ __forceinline__ void cp16(void* dst, const void* src) {
    unsigned d = (unsigned)__cvta_generic_to_shared(dst);
    asm volatile("cp.async.cg.shared.global [%0], [%1], 16;" :: "r"(d), "l"(src));
}

// ===== Pass 1 (round-11 form, measured 22.6us): 448 thr, 4x4 tile, 3-stage pipeline =====
__global__ __launch_bounds__(448, 2) void p1(const float* __restrict__ K,
                                             const float* __restrict__ V) {
    extern __shared__ float4 smem[];

    const int tid   = threadIdx.x;
    const int half  = blockIdx.x;       // rows [0,28) / [28,56)
    const int batch = blockIdx.y;
    const int h   = batch & 7;
    const int win = (batch >> 3) & 1;
    const int tb  = batch >> 4;
    const int base4 = (tb * 256 + h * 32) * HW4 + win * 7;

    const float4* Kp = (const float4*)K;
    const float4* Vp = (const float4*)V;

    int sm_off[4], g_off[4];
    #pragma unroll
    for (int it = 0; it < 4; ++it) {
        int ii = tid + (it & 1) * 448;            // 0..895
        int ch = ii / 28;
        int u  = ii - ch * 28;
        int r  = u / 7;
        int cu = u - r * 7;
        sm_off[it] = (it >= 2 ? CH_F4 : 0) + ch * SROW + u;
        g_off[it]  = ch * HW4 + r * 14 + cu;
    }

    const int g   = tid >> 6;           // 7 groups of 64; group covers p4 {4g..4g+3}
    const int rr  = tid & 63;
    const int d1g = rr >> 3;            // kf broadcast per 8-lane phase
    const int d2g = rr & 7;             // vf step 29 mod 8 = 5: conflict-free

    unsigned long long acc[4][4];
    #pragma unroll
    for (int i = 0; i < 4; i++)
        #pragma unroll
        for (int j = 0; j < 4; j++) acc[i][j] = 0ull;

    #pragma unroll
    for (int pc = 0; pc < 2; ++pc) {
        const int rb = (half * 28 + pc * 4) * 14;
        #pragma unroll
        for (int it = 0; it < 4; ++it)
            cp16(&smem[pc * BUF_F4 + sm_off[it]],
                 (it >= 2 ? Vp : Kp) + base4 + g_off[it] + rb);
        asm volatile("cp.async.commit_group;");
    }

    #pragma unroll 1
    for (int c = 0; c < 7; ++c) {
        if (c < 6) asm volatile("cp.async.wait_group 1;");
        else       asm volatile("cp.async.wait_group 0;");
        __syncthreads();

        if (c + 2 < 7) {
            const int buf = (c + 2) % 3;
            const int rb  = (half * 28 + (c + 2) * 4) * 14;
            #pragma unroll
            for (int it = 0; it < 4; ++it)
                cp16(&smem[buf * BUF_F4 + sm_off[it]],
                     (it >= 2 ? Vp : Kp) + base4 + g_off[it] + rb);
            asm volatile("cp.async.commit_group;");
        }

        const float4* sK = &smem[(c % 3) * BUF_F4];
        const float4* sV = sK + CH_F4;
        #pragma unroll
        for (int qq = 0; qq < 4; ++qq) {
            const int p4 = 4 * g + qq;
            ulonglong2 vf[4];
            #pragma unroll
            for (int j = 0; j < 4; j++)
                vf[j] = *reinterpret_cast<const ulonglong2*>(&sV[(d2g + 8 * j) * SROW + p4]);
            #pragma unroll
            for (int i = 0; i < 4; i++) {
                ulonglong2 kf =
                    *reinterpret_cast<const ulonglong2*>(&sK[(d1g + 8 * i) * SROW + p4]);
                #pragma unroll
                for (int j = 0; j < 4; j++) {
                    FFMA2(acc[i][j], kf.x, vf[j].x);
                    FFMA2(acc[i][j], kf.y, vf[j].y);
                }
            }
        }
    }

    float res[4][4];
    #pragma unroll
    for (int i = 0; i < 4; i++)
        #pragma unroll
        for (int j = 0; j < 4; j++) {
            float2 f = unpack2(acc[i][j]);
            res[i][j] = f.x + f.y;
        }

    __syncthreads();
    float* sRed = (float*)smem;
    if (g) {
        #pragma unroll
        for (int i = 0; i < 4; i++)
            #pragma unroll
            for (int j = 0; j < 4; j++)
                sRed[(g - 1) * 1024 + (d1g + 8 * i) * 32 + d2g + 8 * j] = res[i][j];
    }
    __syncthreads();
    if (!g) {
        float* o = &g_part[((batch << 1) | half) << 10];
        #pragma unroll
        for (int i = 0; i < 4; i++)
            #pragma unroll
            for (int j = 0; j < 4; j++) {
                const int idx = (d1g + 8 * i) * 32 + d2g + 8 * j;
                float s = res[i][j];
                #pragma unroll
                for (int w = 0; w < 6; w++) s += sRed[w * 1024 + idx];
                o[idx] = s;
            }
    }
}

// ===== Pass 2 (round-10 form, measured 18.1us): 1 item/CTA, whole-item q burst =====
// item = b*7 + rb (8-row block). 896 CTAs, 4/SM.
__global__ __launch_bounds__(224, 4) void p2(const float* __restrict__ Q,
                                             float* __restrict__ O) {
    extern __shared__ float4 dsm[];
    float4* sQ = dsm;                          // [1792] f4: 32 ch x 56 quads
    float*  sM = (float*)(dsm + 1792);         // [1024] f32

    const int tid  = threadIdx.x;
    const int item = blockIdx.x;               // 0..895
    const int b    = item / 7;
    const int rb   = item - b * 7;
    const int h    = b & 7;
    const int win  = (b >> 3) & 1;
    const int tb   = b >> 4;
    const int ibase = (tb * 256 + h * 32) * HW4 + win * 7 + rb * 112;

    const float4* Q4 = (const float4*)Q;
    float4* O4 = (float4*)O;

    // burst: whole item's q (1792 f4), 8 cp.async per thread
    #pragma unroll
    for (int t = 0; t < 8; ++t) {
        int i  = tid + t * 224;
        int ch = i / 56;
        int qd = i - ch * 56;
        cp16(&sQ[i], Q4 + ibase + ch * HW4 + (qd / 7) * 14 + (qd - (qd / 7) * 7));
    }
    asm volatile("cp.async.commit_group;");

    // M staging (overlaps q burst): halves reduced + scale folded
    {
        const float4* gp4 = (const float4*)&g_part[b << 11];
        float4* sM4 = (float4*)sM;
        for (int i = tid; i < 256; i += 224) {
            float4 a = gp4[i], bb = gp4[256 + i];
            sM4[i] = make_float4((a.x + bb.x) * SCALE2, (a.y + bb.y) * SCALE2,
                                 (a.z + bb.z) * SCALE2, (a.w + bb.w) * SCALE2);
        }
    }

    asm volatile("cp.async.wait_group 0;");
    __syncthreads();

    const int cg   = tid & 3;                  // ch_out group {cg*8..cg*8+7}
    const int quad = tid >> 2;                 // 0..55
    const int base4 = ibase + (quad / 7) * 14 + (quad - (quad / 7) * 7);

    const float4* q  = &sQ[quad];
    const float*  Ms = &sM[cg * 8];

    unsigned long long acc[4][4];              // [pos-in-quad][ch_out pair]
    #pragma unroll
    for (int p = 0; p < 4; p++)
        #pragma unroll
        for (int j = 0; j < 4; j++) acc[p][j] = 0ull;

    #pragma unroll
    for (int d = 0; d < 32; ++d) {
        float4 qv = q[d * 56];
        const ulonglong2* mr = reinterpret_cast<const ulonglong2*>(Ms + d * 32);
        ulonglong2 m0 = mr[0], m1 = mr[1];
        unsigned long long q0 = pack2(qv.x, qv.x);
        unsigned long long q1 = pack2(qv.y, qv.y);
        unsigned long long q2 = pack2(qv.z, qv.z);
        unsigned long long q3 = pack2(qv.w, qv.w);
        FFMA2(acc[0][0], q0, m0.x); FFMA2(acc[0][1], q0, m0.y);
        FFMA2(acc[0][2], q0, m1.x); FFMA2(acc[0][3], q0, m1.y);
        FFMA2(acc[1][0], q1, m0.x); FFMA2(acc[1][1], q1, m0.y);
        FFMA2(acc[1][2], q1, m1.x); FFMA2(acc[1][3], q1, m1.y);
        FFMA2(acc[2][0], q2, m0.x); FFMA2(acc[2][1], q2, m0.y);
        FFMA2(acc[2][2], q2, m1.x); FFMA2(acc[2][3], q2, m1.y);
        FFMA2(acc[3][0], q3, m0.x); FFMA2(acc[3][1], q3, m0.y);
        FFMA2(acc[3][2], q3, m1.x); FFMA2(acc[3][3], q3, m1.y);
    }

    #pragma unroll
    for (int j = 0; j < 4; ++j) {
        float2 a0 = unpack2(acc[0][j]);
        float2 a1 = unpack2(acc[1][j]);
        float2 a2 = unpack2(acc[2][j]);
        float2 a3 = unpack2(acc[3][j]);
        float4 lo = make_float4(a0.x, a1.x, a2.x, a3.x);
        float4 hi = make_float4(a0.y, a1.y, a2.y, a3.y);
        O4[base4 + (cg * 8 + 2 * j)     * HW4] = lo;
        O4[base4 + (cg * 8 + 2 * j + 1) * HW4] = hi;
    }
}

extern "C" void kernel_launch(void* const* d_in, const int* in_sizes, int n_in,
                              void* d_out, int out_size) {
    const float* q = (const float*)d_in[0];
    const float* k = (const float*)d_in[1];
    const float* v = (const float*)d_in[2];
    float* o = (float*)d_out;

    cudaFuncSetAttribute(p1, cudaFuncAttributeMaxDynamicSharedMemorySize, P1_SMEM);
    cudaFuncSetAttribute(p2, cudaFuncAttributeMaxDynamicSharedMemorySize, P2_SMEM);
    p1<<<dim3(2, NB), 448, P1_SMEM>>>(k, v);
    p2<<<896, 224, P2_SMEM>>>(q, o);
}

// round 14
// speedup vs baseline: 1.3961x; 1.0062x over previous
#include <cuda_runtime.h>

// LePEAttention: out = Q (K^T V) * 2/sqrt(32); no softmax. 128 batches (t,b,win,head),
// each: Q,K,V = [32 ch][1568 pos], pos = 56 rows x 28 cols (win selects col half).

#define HW4    784                 // 3136/4
#define NB     128
#define SROW   29                  // k/v row stride in float4 units (28 + 1 pad)
#define CH_F4  (32 * SROW)
#define BUF_F4 (2 * CH_F4)         // K + V one 4-row chunk
#define P1_SMEM (3 * BUF_F4 * 16)  // triple buffered: 89088 B
#define P2_SMEM 32768              // sQ[1792] f4 (28672 B) + sM[1024] f32 (4096 B)
#define SCALE2 0.35355339059327373f

__device__ float g_part[NB * 2 * 1024];

#define FFMA2(d, a, b) \
    asm("fma.rn.f32x2 %0, %1, %2, %0;" : "+l"(d) : "l"(a), "l"(b))

__device__ __forceinline__ unsigned long long pack2(float x, float y) {
    unsigned long long r;
    asm("mov.b64 %0, {%1,%2};" : "=l"(r) : "f"(x), "f"(y));
    return r;
}
__device__ __forceinline__ float2 unpack2(unsigned long long a) {
    float2 f;
    asm("mov.b64 {%0,%1}, %2;" : "=f"(f.x), "=f"(f.y) : "l"(a));
    return f;
}
__device__ __forceinline__ void cp16(void* dst, const void* src) {
    unsigned d = (unsigned)__cvta_generic_to_shared(dst);
    asm volatile("cp.async.cg.shared.global [%0], [%1], 16;" :: "r"(d), "l"(src));
}

// ===== Pass 1 (round-8 form, measured ~20.3us): 224 thr, 8x4 tile, 3-stage pipeline =====
__global__ __launch_bounds__(224, 2) void p1(const float* __restrict__ K,
                                             const float* __restrict__ V) {
    extern __shared__ float4 smem[];

    const int tid   = threadIdx.x;
    const int half  = blockIdx.x;       // rows [0,28) / [28,56)
    const int batch = blockIdx.y;
    const int h   = batch & 7;
    const int win = (batch >> 3) & 1;
    const int tb  = batch >> 4;
    const int base4 = (tb * 256 + h * 32) * HW4 + win * 7;

    const float4* Kp = (const float4*)K;
    const float4* Vp = (const float4*)V;

    // 8 load slots/thread/chunk (4 K + 4 V); 224*4 = 896 = 32ch * 28 f4
    int sm_off[8], g_off[8];
    #pragma unroll
    for (int it = 0; it < 8; ++it) {
        int ii = tid + (it & 3) * 224;            // 0..895
        int ch = ii / 28;
        int u  = ii - ch * 28;
        int r  = u / 7;
        int cu = u - r * 7;
        sm_off[it] = (it >= 4 ? CH_F4 : 0) + ch * SROW + u;
        g_off[it]  = ch * HW4 + r * 14 + cu;
    }

    const int lane = tid & 31;
    const int warp = tid >> 5;          // 7 warps; warp covers p4 {4w..4w+3}
    const int d1g  = lane & 3;          // k-ch {d1g + 4i}
    const int d2g  = lane >> 2;         // v-ch {d2g + 8j}: step 29 odd -> conflict-free

    unsigned long long acc[8][4];
    #pragma unroll
    for (int i = 0; i < 8; i++)
        #pragma unroll
        for (int j = 0; j < 4; j++) acc[i][j] = 0ull;

    // prologue: chunks 0,1 -> bufs 0,1 (two groups in flight)
    #pragma unroll
    for (int pc = 0; pc < 2; ++pc) {
        const int rb = (half * 28 + pc * 4) * 14;
        #pragma unroll
        for (int it = 0; it < 8; ++it)
            cp16(&smem[pc * BUF_F4 + sm_off[it]],
                 (it >= 4 ? Vp : Kp) + base4 + g_off[it] + rb);
        asm volatile("cp.async.commit_group;");
    }

    #pragma unroll 1
    for (int c = 0; c < 7; ++c) {
        if (c < 6) asm volatile("cp.async.wait_group 1;");
        else       asm volatile("cp.async.wait_group 0;");
        __syncthreads();

        if (c + 2 < 7) {
            const int buf = (c + 2) % 3;
            const int rb  = (half * 28 + (c + 2) * 4) * 14;
            #pragma unroll
            for (int it = 0; it < 8; ++it)
                cp16(&smem[buf * BUF_F4 + sm_off[it]],
                     (it >= 4 ? Vp : Kp) + base4 + g_off[it] + rb);
            asm volatile("cp.async.commit_group;");
        }

        const float4* sK = &smem[(c % 3) * BUF_F4];
        const float4* sV = sK + CH_F4;
        #pragma unroll
        for (int qq = 0; qq < 4; ++qq) {
            const int p4 = 4 * warp + qq;
            ulonglong2 vf[4];
            #pragma unroll
            for (int j = 0; j < 4; j++)
                vf[j] = *reinterpret_cast<const ulonglong2*>(&sV[(d2g + 8 * j) * SROW + p4]);
            #pragma unroll
            for (int i = 0; i < 8; i++) {
                ulonglong2 kf =
                    *reinterpret_cast<const ulonglong2*>(&sK[(d1g + 4 * i) * SROW + p4]);
                #pragma unroll
                for (int j = 0; j < 4; j++) {
                    FFMA2(acc[i][j], kf.x, vf[j].x);
                    FFMA2(acc[i][j], kf.y, vf[j].y);
                }
            }
        }
    }

    float res[8][4];
    #pragma unroll
    for (int i = 0; i < 8; i++)
        #pragma unroll
        for (int j = 0; j < 4; j++) {
            float2 f = unpack2(acc[i][j]);
            res[i][j] = f.x + f.y;
        }

    __syncthreads();
    float* sRed = (float*)smem;
    if (warp) {
        #pragma unroll
        for (int i = 0; i < 8; i++)
            #pragma unroll
            for (int j = 0; j < 4; j++)
                sRed[(warp - 1) * 1024 + (d1g + 4 * i) * 32 + d2g + 8 * j] = res[i][j];
    }
    __syncthreads();
    if (!warp) {
        float* o = &g_part[((batch << 1) | half) << 10];
        #pragma unroll
        for (int i = 0; i < 8; i++)
            #pragma unroll
            for (int j = 0; j < 4; j++) {
                const int idx = (d1g + 4 * i) * 32 + d2g + 8 * j;
                float s = res[i][j];
                #pragma unroll
                for (int w = 0; w < 6; w++) s += sRed[w * 1024 + idx];
                o[idx] = s;
            }
    }
}

// ===== Pass 2 (round-10 form, measured ~18.1us): 1 item/CTA, whole-item q burst =====
// item = b*7 + rb (8-row block). 896 CTAs, 4/SM.
__global__ __launch_bounds__(224, 4) void p2(const float* __restrict__ Q,
                                             float* __restrict__ O) {
    extern __shared__ float4 dsm[];
    float4* sQ = dsm;                          // [1792] f4: 32 ch x 56 quads
    float*  sM = (float*)(dsm + 1792);         // [1024] f32

    const int tid  = threadIdx.x;
    const int item = blockIdx.x;               // 0..895
    const int b    = item / 7;
    const int rb   = item - b * 7;
    const int h    = b & 7;
    const int win  = (b >> 3) & 1;
    const int tb   = b >> 4;
    const int ibase = (tb * 256 + h * 32) * HW4 + win * 7 + rb * 112;

    const float4* Q4 = (const float4*)Q;
    float4* O4 = (float4*)O;

    // burst: whole item's q (1792 f4), 8 cp.async per thread
    #pragma unroll
    for (int t = 0; t < 8; ++t) {
        int i  = tid + t * 224;
        int ch = i / 56;
        int qd = i - ch * 56;
        cp16(&sQ[i], Q4 + ibase + ch * HW4 + (qd / 7) * 14 + (qd - (qd / 7) * 7));
    }
    asm volatile("cp.async.commit_group;");

    // M staging (overlaps q burst): halves reduced + scale folded
    {
        const float4* gp4 = (const float4*)&g_part[b << 11];
        float4* sM4 = (float4*)sM;
        for (int i = tid; i < 256; i += 224) {
            float4 a = gp4[i], bb = gp4[256 + i];
            sM4[i] = make_float4((a.x + bb.x) * SCALE2, (a.y + bb.y) * SCALE2,
                                 (a.z + bb.z) * SCALE2, (a.w + bb.w) * SCALE2);
        }
    }

    asm volatile("cp.async.wait_group 0;");
    __syncthreads();

    const int cg   = tid & 3;                  // ch_out group {cg*8..cg*8+7}
    const int quad = tid >> 2;                 // 0..55
    const int base4 = ibase + (quad / 7) * 14 + (quad - (quad / 7) * 7);

    const float4* q  = &sQ[quad];
    const float*  Ms = &sM[cg * 8];

    unsigned long long acc[4][4];              // [pos-in-quad][ch_out pair]
    #pragma unroll
    for (int p = 0; p < 4; p++)
        #pragma unroll
        for (int j = 0; j < 4; j++) acc[p][j] = 0ull;

    #pragma unroll
    for (int d = 0; d < 32; ++d) {
        float4 qv = q[d * 56];
        const ulonglong2* mr = reinterpret_cast<const ulonglong2*>(Ms + d * 32);
        ulonglong2 m0 = mr[0], m1 = mr[1];
        unsigned long long q0 = pack2(qv.x, qv.x);
        unsigned long long q1 = pack2(qv.y, qv.y);
        unsigned long long q2 = pack2(qv.z, qv.z);
        unsigned long long q3 = pack2(qv.w, qv.w);
        FFMA2(acc[0][0], q0, m0.x); FFMA2(acc[0][1], q0, m0.y);
        FFMA2(acc[0][2], q0, m1.x); FFMA2(acc[0][3], q0, m1.y);
        FFMA2(acc[1][0], q1, m0.x); FFMA2(acc[1][1], q1, m0.y);
        FFMA2(acc[1][2], q1, m1.x); FFMA2(acc[1][3], q1, m1.y);
        FFMA2(acc[2][0], q2, m0.x); FFMA2(acc[2][1], q2, m0.y);
        FFMA2(acc[2][2], q2, m1.x); FFMA2(acc[2][3], q2, m1.y);
        FFMA2(acc[3][0], q3, m0.x); FFMA2(acc[3][1], q3, m0.y);
        FFMA2(acc[3][2], q3, m1.x); FFMA2(acc[3][3], q3, m1.y);
    }

    #pragma unroll
    for (int j = 0; j < 4; ++j) {
        float2 a0 = unpack2(acc[0][j]);
        float2 a1 = unpack2(acc[1][j]);
        float2 a2 = unpack2(acc[2][j]);
        float2 a3 = unpack2(acc[3][j]);
        float4 lo = make_float4(a0.x, a1.x, a2.x, a3.x);
        float4 hi = make_float4(a0.y, a1.y, a2.y, a3.y);
        O4[base4 + (cg * 8 + 2 * j)     * HW4] = lo;
        O4[base4 + (cg * 8 + 2 * j + 1) * HW4] = hi;
    }
}

extern "C" void kernel_launch(void* const* d_in, const int* in_sizes, int n_in,
                              void* d_out, int out_size) {
    const float* q = (const float*)d_in[0];
    const float* k = (const float*)d_in[1];
    const float* v = (const float*)d_in[2];
    float* o = (float*)d_out;

    cudaFuncSetAttribute(p1, cudaFuncAttributeMaxDynamicSharedMemorySize, P1_SMEM);
    cudaFuncSetAttribute(p2, cudaFuncAttributeMaxDynamicSharedMemorySize, P2_SMEM);
    p1<<<dim3(2, NB), 224, P1_SMEM>>>(k, v);
    p2<<<896, 224, P2_SMEM>>>(q, o);
}